// round 13
// baseline (speedup 1.0000x reference)
#include <cuda_runtime.h>
#include <cuda_fp16.h>
#include <cstdint>

// ---------------- problem constants ----------------
#define T_ROWS   786432
#define NIN      50          // GEMM1 reduction dim (padded to 56 in smem)
#define KFEAT    400         // hidden features = 25 m16 feature-tiles
#define CC       10          // classes
#define JP       24          // pooling window = 3 n8-tiles
#define SC_ROWS  384         // superchunk rows = 16 segments
#define SEGS     16
#define NSC      (T_ROWS / SC_ROWS)      // 2048
#define NTHREADS 640
#define FT_PER_W 5           // 25 ftiles / 5 groups
#define GRID     152
#define KS2      25          // GEMM2 k16 steps (400/16)
#define ONESH2   0x3C003C00u // half2(1.0, 1.0)

// ---------------- smem layout (bytes) ----------------
// 112B row stride (7 x 16B chunks): 28 words mod 32 -> rows hit disjoint banks,
// ldmatrix conflict-free WITHOUT swizzle. k50..55 zero-padded.
#define ROWB       112
#define X_OFF      0
#define X_BYTES    (SC_ROWS * ROWB)          // 43008
#define W1_OFF     (X_OFF + X_BYTES)
#define W1_BYTES   (KFEAT * ROWB)            // 44800
#define F16_OFF    (W1_OFF + W1_BYTES)       // 87808
#define F16_STRIDE 816                       // 51 chunks, conflict-free
#define F16_BYTES  (SEGS * F16_STRIDE)       // 13056
#define W2F_OFF    (F16_OFF + F16_BYTES)     // 100864
#define W2F_BYTES  (2 * KS2 * 2 * 32 * 4)    // 12800
#define STAGE_OFF  (W2F_OFF + W2F_BYTES)     // 113664
#define STAGE_BYTES (SC_ROWS * NIN * 4)      // 76800
#define SMEM_TOTAL (STAGE_OFF + STAGE_BYTES) // 190464

__device__ __forceinline__ uint32_t smem_u32(const void* p) {
    uint32_t a;
    asm("{ .reg .u64 t; cvta.to.shared.u64 t, %1; cvt.u32.u64 %0, t; }" : "=r"(a) : "l"(p));
    return a;
}
__device__ __forceinline__ void cp16(uint32_t dst, const void* src) {
    asm volatile("cp.async.cg.shared.global [%0], [%1], 16;" :: "r"(dst), "l"(src));
}
// relu + pack two fp32 into fp16x2 (relu commutes with rounding at 0)
__device__ __forceinline__ uint32_t relu_pack(float lo, float hi) {
    half2 h = __floats2half2_rn(lo, hi);
    half2 z = __half2half2(__ushort_as_half(0));
    h = __hmax2(h, z);
    return *(uint32_t*)&h;
}

__global__ void __launch_bounds__(NTHREADS, 1)
classifier_mma6_kernel(const float* __restrict__ x,
                       const float* __restrict__ W1,
                       const float* __restrict__ W2,
                       float* __restrict__ out)
{
    extern __shared__ char smem[];

    const int tid  = threadIdx.x;
    const int wid  = tid >> 5;
    const int lane = tid & 31;
    const uint32_t sbase = smem_u32(smem);
    const uint32_t stage = sbase + STAGE_OFF;

    // ---- zero X & W1 (covers k50..55 padding, persists) ----
    for (int i = tid; i < (X_BYTES + W1_BYTES) / 4; i += NTHREADS)
        ((uint32_t*)smem)[i] = 0;
    __syncthreads();

    // ---- load W1 -> smem fp16 (plain 112B-stride layout) ----
    for (int i = tid; i < KFEAT * 25; i += NTHREADS) {
        int f = i / 25, p = i - f * 25;
        float2 v = *(const float2*)(W1 + f * NIN + 2 * p);
        *(half2*)(smem + W1_OFF + f * ROWB + p * 4) = __float22half2_rn(v);
    }

    // ---- pre-pack W2 into B-fragment order (fp16), warps 0 & 1 ----
    if (wid < 2) {
        const int n = wid * 8 + (lane >> 2);
        #pragma unroll 1
        for (int ks = 0; ks < KS2; ks++) {
            #pragma unroll
            for (int r = 0; r < 2; r++) {
                const int k = ks * 16 + (lane & 3) * 2 + r * 8;
                float lo = 0.f, hi = 0.f;
                if (n < CC) { lo = W2[n * KFEAT + k]; hi = W2[n * KFEAT + k + 1]; }
                half2 h = __floats2half2_rn(lo, hi);
                ((uint32_t*)(smem + W2F_OFF))[((wid * KS2 + ks) * 2 + r) * 32 + lane] =
                    *(uint32_t*)&h;
            }
        }
    }

    // ---- prologue: stage x for first superchunk ----
    {
        const char* xg = (const char*)x + (size_t)blockIdx.x * STAGE_BYTES;
        for (int i = tid; i < STAGE_BYTES / 16; i += NTHREADS)
            cp16(stage + i * 16, xg + i * 16);
        asm volatile("cp.async.commit_group;" ::: "memory");
        asm volatile("cp.async.wait_group 0;" ::: "memory");
    }
    __syncthreads();

    // ---- per-lane invariants ----
    const int rrA = lane & 15;          // A (W1) row within ftile
    const int chi = lane >> 4;          // A chunk-half selector
    const int nl  = lane & 7;           // B (x) row-in-ntile
    const int blk = lane >> 3;          // B chunk index (x4 load)
    const int bl2 = (lane >> 3) & 1;    // B chunk sub-index (x2 load)
    const int wr  = wid / 5;            // seg-group 0..3
    const int wc  = wid - wr * 5;       // ftile-group 0..4
    const bool pool_leader = ((lane & 3) == 0);
    const int prow = lane >> 2;         // pooled feature row (0..7)

    int prev_sc = -1;

    for (int sc = blockIdx.x; sc < NSC; sc += GRID) {
        // ---- phase (a): warps 2..19 convert staging->X ; warps 0,1 GEMM2(prev) ----
        if (wid >= 2) {
            #pragma unroll 1
            for (int i = tid - 64; i < SC_ROWS * 25; i += NTHREADS - 64) {
                int r = i / 25, p = i - r * 25;
                float2 v = *(const float2*)(smem + STAGE_OFF + r * 200 + 8 * p);
                *(half2*)(smem + X_OFF + r * ROWB + p * 4) = __float22half2_rn(v);
            }
        } else if (prev_sc >= 0) {
            float e0 = 0.f, e1 = 0.f, e2 = 0.f, e3 = 0.f;
            const uint32_t arow = sbase + F16_OFF + (uint32_t)(lane & 15) * F16_STRIDE
                                + (uint32_t)(lane >> 4) * 16;
            const uint32_t* w2f = (const uint32_t*)(smem + W2F_OFF) + (wid * KS2 * 2) * 32 + lane;
            #pragma unroll 5
            for (int ks = 0; ks < KS2; ks++) {
                uint32_t a0, a1, a2, a3;
                asm volatile("ldmatrix.sync.aligned.m8n8.x4.shared.b16 {%0,%1,%2,%3}, [%4];"
                             : "=r"(a0), "=r"(a1), "=r"(a2), "=r"(a3)
                             : "r"(arow + ks * 32));
                const uint32_t b0 = w2f[(ks * 2) * 32];
                const uint32_t b1 = w2f[(ks * 2 + 1) * 32];
                asm volatile(
                    "mma.sync.aligned.m16n8k16.row.col.f32.f16.f16.f32 "
                    "{%0,%1,%2,%3}, {%4,%5,%6,%7}, {%8,%9}, {%0,%1,%2,%3};"
                    : "+f"(e0), "+f"(e1), "+f"(e2), "+f"(e3)
                    : "r"(a0), "r"(a1), "r"(a2), "r"(a3), "r"(b0), "r"(b1));
            }
            const int n = wid * 8 + 2 * (lane & 3);
            if (n < CC) {
                const int r0 = lane >> 2;
                float2 v0 = {e0, e1}, v1 = {e2, e3};
                *(float2*)(out + (size_t)(prev_sc * SEGS + r0) * CC + n)     = v0;
                *(float2*)(out + (size_t)(prev_sc * SEGS + r0 + 8) * CC + n) = v1;
            }
        }
        __syncthreads();   // X ready; staging consumed; gemm2(prev) done

        // ---- stream next superchunk's x into staging ----
        {
            const int nsc = sc + GRID;
            if (nsc < NSC) {
                const char* xg = (const char*)x + (size_t)nsc * STAGE_BYTES;
                #pragma unroll 1
                for (int i = tid; i < STAGE_BYTES / 16; i += NTHREADS)
                    cp16(stage + i * 16, xg + i * 16);
            }
            asm volatile("cp.async.commit_group;" ::: "memory");
        }

        // ---- GEMM1 + relu + MMA-pooling ----
        #pragma unroll 1
        for (int sp = 0; sp < 2; sp++) {
            const int s0 = wr * 4 + 2 * sp;     // this warp's segment pair

            // B fragments: 2 segs x 3 n-tiles x (6 k16-pair regs + 1 k8 reg)
            uint32_t b[2][3][7];
            #pragma unroll
            for (int ss = 0; ss < 2; ss++) {
                #pragma unroll
                for (int nt = 0; nt < 3; nt++) {
                    const uint32_t rowa = sbase + X_OFF
                        + (uint32_t)((s0 + ss) * JP + nt * 8 + nl) * ROWB;
                    asm volatile("ldmatrix.sync.aligned.m8n8.x4.shared.b16 {%0,%1,%2,%3}, [%4];"
                                 : "=r"(b[ss][nt][0]), "=r"(b[ss][nt][1]),
                                   "=r"(b[ss][nt][2]), "=r"(b[ss][nt][3])
                                 : "r"(rowa + blk * 16));
                    asm volatile("ldmatrix.sync.aligned.m8n8.x2.shared.b16 {%0,%1}, [%2];"
                                 : "=r"(b[ss][nt][4]), "=r"(b[ss][nt][5])
                                 : "r"(rowa + (4 + bl2) * 16));
                    asm volatile("ldmatrix.sync.aligned.m8n8.x1.shared.b16 {%0}, [%1];"
                                 : "=r"(b[ss][nt][6]) : "r"(rowa + 96));
                }
            }

            #pragma unroll 1
            for (int fi = 0; fi < FT_PER_W; fi++) {
                const int F = (wc * FT_PER_W + fi) * 16;
                const uint32_t abase = sbase + W1_OFF + (uint32_t)(F + rrA) * ROWB;

                uint32_t a[3][4];   // k16 steps 0..2
                #pragma unroll
                for (int ks = 0; ks < 3; ks++) {
                    asm volatile("ldmatrix.sync.aligned.m8n8.x4.shared.b16 {%0,%1,%2,%3}, [%4];"
                                 : "=r"(a[ks][0]), "=r"(a[ks][1]),
                                   "=r"(a[ks][2]), "=r"(a[ks][3])
                                 : "r"(abase + (2 * ks + chi) * 16));
                }
                uint32_t a8[2];     // k8 step: chunk 6 (k48..55)
                asm volatile("ldmatrix.sync.aligned.m8n8.x2.shared.b16 {%0,%1}, [%2];"
                             : "=r"(a8[0]), "=r"(a8[1]) : "r"(abase + 96));

                // relu'd fp16 packs per [seg][nt][lo/hi]
                uint32_t ph[2][3][2];
                #pragma unroll
                for (int nt = 0; nt < 3; nt++) {
                    float c0 = 0.f, c1 = 0.f, c2 = 0.f, c3 = 0.f;
                    float d0 = 0.f, d1 = 0.f, d2 = 0.f, d3 = 0.f;
                    #pragma unroll
                    for (int ks = 0; ks < 3; ks++) {
                        asm volatile(
                            "mma.sync.aligned.m16n8k16.row.col.f32.f16.f16.f32 "
                            "{%0,%1,%2,%3}, {%4,%5,%6,%7}, {%8,%9}, {%0,%1,%2,%3};"
                            : "+f"(c0), "+f"(c1), "+f"(c2), "+f"(c3)
                            : "r"(a[ks][0]), "r"(a[ks][1]), "r"(a[ks][2]), "r"(a[ks][3]),
                              "r"(b[0][nt][2 * ks]), "r"(b[0][nt][2 * ks + 1]));
                        asm volatile(
                            "mma.sync.aligned.m16n8k16.row.col.f32.f16.f16.f32 "
                            "{%0,%1,%2,%3}, {%4,%5,%6,%7}, {%8,%9}, {%0,%1,%2,%3};"
                            : "+f"(d0), "+f"(d1), "+f"(d2), "+f"(d3)
                            : "r"(a[ks][0]), "r"(a[ks][1]), "r"(a[ks][2]), "r"(a[ks][3]),
                              "r"(b[1][nt][2 * ks]), "r"(b[1][nt][2 * ks + 1]));
                    }
                    asm volatile(
                        "mma.sync.aligned.m16n8k8.row.col.f32.f16.f16.f32 "
                        "{%0,%1,%2,%3}, {%4,%5}, {%6}, {%0,%1,%2,%3};"
                        : "+f"(c0), "+f"(c1), "+f"(c2), "+f"(c3)
                        : "r"(a8[0]), "r"(a8[1]), "r"(b[0][nt][6]));
                    asm volatile(
                        "mma.sync.aligned.m16n8k8.row.col.f32.f16.f16.f32 "
                        "{%0,%1,%2,%3}, {%4,%5}, {%6}, {%0,%1,%2,%3};"
                        : "+f"(d0), "+f"(d1), "+f"(d2), "+f"(d3)
                        : "r"(a8[0]), "r"(a8[1]), "r"(b[1][nt][6]));

                    ph[0][nt][0] = relu_pack(c0, c1);
                    ph[0][nt][1] = relu_pack(c2, c3);
                    ph[1][nt][0] = relu_pack(d0, d1);
                    ph[1][nt][1] = relu_pack(d2, d3);
                }

                // pool via MMA against all-ones B: sums the 24 rows in fp32
                float p0 = 0.f, p1 = 0.f, p2 = 0.f, p3 = 0.f;
                float q0 = 0.f, q1 = 0.f, q2 = 0.f, q3 = 0.f;
                asm volatile(
                    "mma.sync.aligned.m16n8k16.row.col.f32.f16.f16.f32 "
                    "{%0,%1,%2,%3}, {%4,%5,%6,%7}, {%8,%9}, {%0,%1,%2,%3};"
                    : "+f"(p0), "+f"(p1), "+f"(p2), "+f"(p3)
                    : "r"(ph[0][0][0]), "r"(ph[0][0][1]), "r"(ph[0][1][0]), "r"(ph[0][1][1]),
                      "r"(ONESH2), "r"(ONESH2));
                asm volatile(
                    "mma.sync.aligned.m16n8k8.row.col.f32.f16.f16.f32 "
                    "{%0,%1,%2,%3}, {%4,%5}, {%6}, {%0,%1,%2,%3};"
                    : "+f"(p0), "+f"(p1), "+f"(p2), "+f"(p3)
                    : "r"(ph[0][2][0]), "r"(ph[0][2][1]), "r"(ONESH2));
                asm volatile(
                    "mma.sync.aligned.m16n8k16.row.col.f32.f16.f16.f32 "
                    "{%0,%1,%2,%3}, {%4,%5,%6,%7}, {%8,%9}, {%0,%1,%2,%3};"
                    : "+f"(q0), "+f"(q1), "+f"(q2), "+f"(q3)
                    : "r"(ph[1][0][0]), "r"(ph[1][0][1]), "r"(ph[1][1][0]), "r"(ph[1][1][1]),
                      "r"(ONESH2), "r"(ONESH2));
                asm volatile(
                    "mma.sync.aligned.m16n8k8.row.col.f32.f16.f16.f32 "
                    "{%0,%1,%2,%3}, {%4,%5}, {%6}, {%0,%1,%2,%3};"
                    : "+f"(q0), "+f"(q1), "+f"(q2), "+f"(q3)
                    : "r"(ph[1][2][0]), "r"(ph[1][2][1]), "r"(ONESH2));
                (void)p1; (void)p3; (void)q1; (void)q3;

                if (pool_leader) {   // col 0 lanes hold the pooled sums
                    char* f0 = smem + F16_OFF + s0 * F16_STRIDE + (F + prow) * 2;
                    char* f1 = smem + F16_OFF + (s0 + 1) * F16_STRIDE + (F + prow) * 2;
                    *(half*)(f0)      = __float2half(p0 * (1.0f / (float)JP));
                    *(half*)(f0 + 16) = __float2half(p2 * (1.0f / (float)JP));
                    *(half*)(f1)      = __float2half(q0 * (1.0f / (float)JP));
                    *(half*)(f1 + 16) = __float2half(q2 * (1.0f / (float)JP));
                }
            }
        }

        // ---- staging refilled; feat16 complete ----
        asm volatile("cp.async.wait_group 0;" ::: "memory");
        __syncthreads();
        prev_sc = sc;
    }

    // ---- epilogue GEMM2 for the last superchunk ----
    if (wid < 2 && prev_sc >= 0) {
        float e0 = 0.f, e1 = 0.f, e2 = 0.f, e3 = 0.f;
        const uint32_t arow = sbase + F16_OFF + (uint32_t)(lane & 15) * F16_STRIDE
                            + (uint32_t)(lane >> 4) * 16;
        const uint32_t* w2f = (const uint32_t*)(smem + W2F_OFF) + (wid * KS2 * 2) * 32 + lane;
        #pragma unroll 5
        for (int ks = 0; ks < KS2; ks++) {
            uint32_t a0, a1, a2, a3;
            asm volatile("ldmatrix.sync.aligned.m8n8.x4.shared.b16 {%0,%1,%2,%3}, [%4];"
                         : "=r"(a0), "=r"(a1), "=r"(a2), "=r"(a3)
                         : "r"(arow + ks * 32));
            const uint32_t b0 = w2f[(ks * 2) * 32];
            const uint32_t b1 = w2f[(ks * 2 + 1) * 32];
            asm volatile(
                "mma.sync.aligned.m16n8k16.row.col.f32.f16.f16.f32 "
                "{%0,%1,%2,%3}, {%4,%5,%6,%7}, {%8,%9}, {%0,%1,%2,%3};"
                : "+f"(e0), "+f"(e1), "+f"(e2), "+f"(e3)
                : "r"(a0), "r"(a1), "r"(a2), "r"(a3), "r"(b0), "r"(b1));
        }
        const int n = wid * 8 + 2 * (lane & 3);
        if (n < CC) {
            const int r0 = lane >> 2;
            float2 v0 = {e0, e1}, v1 = {e2, e3};
            *(float2*)(out + (size_t)(prev_sc * SEGS + r0) * CC + n)     = v0;
            *(float2*)(out + (size_t)(prev_sc * SEGS + r0 + 8) * CC + n) = v1;
        }
    }
}

extern "C" void kernel_launch(void* const* d_in, const int* in_sizes, int n_in,
                              void* d_out, int out_size)
{
    const float* x  = (const float*)d_in[0];
    const float* W1 = (const float*)d_in[1];
    const float* W2 = (const float*)d_in[2];
    float* out = (float*)d_out;

    cudaFuncSetAttribute(classifier_mma6_kernel,
                         cudaFuncAttributeMaxDynamicSharedMemorySize, SMEM_TOTAL);
    classifier_mma6_kernel<<<GRID, NTHREADS, SMEM_TOTAL>>>(x, W1, W2, out);
}

// round 17
// speedup vs baseline: 1.0354x; 1.0354x over previous
#include <cuda_runtime.h>
#include <cuda_fp16.h>
#include <cstdint>

// ---------------- problem constants ----------------
#define T_ROWS   786432
#define NIN      50          // GEMM1 reduction dim (padded to 56 in smem)
#define KFEAT    400         // hidden features = 25 m16 feature-tiles
#define CC       10          // classes
#define JP       24          // pooling window = 3 n8-tiles
#define SC_ROWS  384         // superchunk rows = 16 segments
#define SEGS     16
#define NSC      (T_ROWS / SC_ROWS)      // 2048
#define NTHREADS 640
#define FT_PER_W 5           // 25 ftiles / 5 groups
#define GRID     152
#define KS2      25          // GEMM2 k16 steps (400/16)
#define ONESH2   0x3C003C00u // half2(1.0, 1.0)

// group geometry: 4 seg-groups x 5 warps; group wr owns rows [96*wr, 96*wr+96)
#define GROUP_THREADS 160
#define GROUP_ROWS    96
#define GROUP_HALF2   (GROUP_ROWS * 25)      // 2400 half2 converts per group
#define GROUP_CP16    1200                   // 96 rows * 200B / 16B

// ---------------- smem layout (bytes) ----------------
#define ROWB       112
#define X_OFF      0
#define X_BYTES    (SC_ROWS * ROWB)          // 43008
#define W1_OFF     (X_OFF + X_BYTES)
#define W1_BYTES   (KFEAT * ROWB)            // 44800
#define F16_OFF    (W1_OFF + W1_BYTES)       // 87808
#define F16_STRIDE 816
#define F16_BYTES  (SEGS * F16_STRIDE)       // 13056
#define W2F_OFF    (F16_OFF + F16_BYTES)     // 100864
#define W2F_BYTES  (2 * KS2 * 2 * 32 * 4)    // 12800
#define STAGE_OFF  (W2F_OFF + W2F_BYTES)     // 113664
#define STAGE_BYTES (SC_ROWS * NIN * 4)      // 76800
#define SMEM_TOTAL (STAGE_OFF + STAGE_BYTES) // 190464

__device__ __forceinline__ uint32_t smem_u32(const void* p) {
    uint32_t a;
    asm("{ .reg .u64 t; cvta.to.shared.u64 t, %1; cvt.u32.u64 %0, t; }" : "=r"(a) : "l"(p));
    return a;
}
__device__ __forceinline__ void cp16(uint32_t dst, const void* src) {
    asm volatile("cp.async.cg.shared.global [%0], [%1], 16;" :: "r"(dst), "l"(src));
}
__device__ __forceinline__ uint32_t relu_pack(float lo, float hi) {
    half2 h = __floats2half2_rn(lo, hi);
    half2 z = __half2half2(__ushort_as_half(0));
    h = __hmax2(h, z);
    return *(uint32_t*)&h;
}

__global__ void __launch_bounds__(NTHREADS, 1)
classifier_mma7_kernel(const float* __restrict__ x,
                       const float* __restrict__ W1,
                       const float* __restrict__ W2,
                       float* __restrict__ out)
{
    extern __shared__ char smem[];

    const int tid  = threadIdx.x;
    const int wid  = tid >> 5;
    const int lane = tid & 31;
    const uint32_t sbase = smem_u32(smem);
    const uint32_t stage = sbase + STAGE_OFF;

    // ---- zero X & W1 (covers k50..55 padding, persists) ----
    for (int i = tid; i < (X_BYTES + W1_BYTES) / 4; i += NTHREADS)
        ((uint32_t*)smem)[i] = 0;
    __syncthreads();

    // ---- load W1 -> smem fp16 (plain 112B-stride layout) ----
    for (int i = tid; i < KFEAT * 25; i += NTHREADS) {
        int f = i / 25, p = i - f * 25;
        float2 v = *(const float2*)(W1 + f * NIN + 2 * p);
        *(half2*)(smem + W1_OFF + f * ROWB + p * 4) = __float22half2_rn(v);
    }

    // ---- pre-pack W2 into B-fragment order (fp16), warps 0 & 1 ----
    if (wid < 2) {
        const int n = wid * 8 + (lane >> 2);
        #pragma unroll 1
        for (int ks = 0; ks < KS2; ks++) {
            #pragma unroll
            for (int r = 0; r < 2; r++) {
                const int k = ks * 16 + (lane & 3) * 2 + r * 8;
                float lo = 0.f, hi = 0.f;
                if (n < CC) { lo = W2[n * KFEAT + k]; hi = W2[n * KFEAT + k + 1]; }
                half2 h = __floats2half2_rn(lo, hi);
                ((uint32_t*)(smem + W2F_OFF))[((wid * KS2 + ks) * 2 + r) * 32 + lane] =
                    *(uint32_t*)&h;
            }
        }
    }

    // ---- prologue: stage x for first superchunk ----
    {
        const char* xg = (const char*)x + (size_t)blockIdx.x * STAGE_BYTES;
        for (int i = tid; i < STAGE_BYTES / 16; i += NTHREADS)
            cp16(stage + i * 16, xg + i * 16);
        asm volatile("cp.async.commit_group;" ::: "memory");
        asm volatile("cp.async.wait_group 0;" ::: "memory");
    }
    __syncthreads();

    // ---- per-lane invariants ----
    const int rrA = lane & 15;          // A (W1) row within ftile
    const int chi = lane >> 4;          // A chunk-half selector
    const int nl  = lane & 7;           // B (x) row-in-ntile
    const int blk = lane >> 3;          // B chunk index (x4 load)
    const int bl2 = (lane >> 3) & 1;    // B chunk sub-index (x2 load)
    const int wr  = wid / 5;            // seg-group 0..3
    const int wc  = wid - wr * 5;       // ftile-group 0..4
    const bool pool_leader = ((lane & 3) == 0);
    const int prow = lane >> 2;         // pooled feature row (0..7)

    // group-local work-partition indices
    const bool is_g2w = (wid < 2);                 // GEMM2 warps (group 0)
    const int  gl     = tid - wr * GROUP_THREADS;  // 0..159 within group (all threads)
    // convert pass: group 0 uses only warps 2..4 (96 threads)
    const int  cvt_start  = (wr == 0) ? (tid - 64) : gl;   // valid only when !is_g2w
    const int  cvt_stride = (wr == 0) ? 96 : GROUP_THREADS;

    int prev_sc = -1;

    for (int sc = blockIdx.x; sc < NSC; sc += GRID) {
        // ---- group-local convert (staging fp32 -> X fp16); warps 0,1: GEMM2(prev) ----
        if (!is_g2w) {
            const int rbase = wr * GROUP_ROWS;
            #pragma unroll 1
            for (int j = cvt_start; j < GROUP_HALF2; j += cvt_stride) {
                int rl = j / 25, p = j - rl * 25;
                int r = rbase + rl;
                float2 v = *(const float2*)(smem + STAGE_OFF + r * 200 + 8 * p);
                *(half2*)(smem + X_OFF + r * ROWB + p * 4) = __float22half2_rn(v);
            }
        } else if (prev_sc >= 0) {
            float e0 = 0.f, e1 = 0.f, e2 = 0.f, e3 = 0.f;
            const uint32_t arow = sbase + F16_OFF + (uint32_t)(lane & 15) * F16_STRIDE
                                + (uint32_t)(lane >> 4) * 16;
            const uint32_t* w2f = (const uint32_t*)(smem + W2F_OFF) + (wid * KS2 * 2) * 32 + lane;
            #pragma unroll 5
            for (int ks = 0; ks < KS2; ks++) {
                uint32_t a0, a1, a2, a3;
                asm volatile("ldmatrix.sync.aligned.m8n8.x4.shared.b16 {%0,%1,%2,%3}, [%4];"
                             : "=r"(a0), "=r"(a1), "=r"(a2), "=r"(a3)
                             : "r"(arow + ks * 32));
                const uint32_t b0 = w2f[(ks * 2) * 32];
                const uint32_t b1 = w2f[(ks * 2 + 1) * 32];
                asm volatile(
                    "mma.sync.aligned.m16n8k16.row.col.f32.f16.f16.f32 "
                    "{%0,%1,%2,%3}, {%4,%5,%6,%7}, {%8,%9}, {%0,%1,%2,%3};"
                    : "+f"(e0), "+f"(e1), "+f"(e2), "+f"(e3)
                    : "r"(a0), "r"(a1), "r"(a2), "r"(a3), "r"(b0), "r"(b1));
            }
            const int n = wid * 8 + 2 * (lane & 3);
            if (n < CC) {
                const int r0 = lane >> 2;
                float2 v0 = {e0, e1}, v1 = {e2, e3};
                *(float2*)(out + (size_t)(prev_sc * SEGS + r0) * CC + n)     = v0;
                *(float2*)(out + (size_t)(prev_sc * SEGS + r0 + 8) * CC + n) = v1;
            }
        }
        // group barrier: this group's X rows ready (GEMM2 warps also arrive here)
        asm volatile("bar.sync %0, %1;" :: "r"(wr + 1), "r"(GROUP_THREADS) : "memory");

        // ---- group-local staging refill for next superchunk (overlaps GEMM1) ----
        // ALL 160 group threads participate (gl is non-negative for every thread).
        {
            const int nsc = sc + GRID;
            if (nsc < NSC) {
                const char* xg = (const char*)x + (size_t)nsc * STAGE_BYTES;
                const int i0 = wr * GROUP_CP16;
                #pragma unroll 1
                for (int i = i0 + gl; i < i0 + GROUP_CP16; i += GROUP_THREADS)
                    cp16(stage + i * 16, xg + i * 16);
            }
            asm volatile("cp.async.commit_group;" ::: "memory");
        }

        // ---- GEMM1 + relu + MMA-pooling ----
        #pragma unroll 1
        for (int sp = 0; sp < 2; sp++) {
            const int s0 = wr * 4 + 2 * sp;     // this warp's segment pair

            uint32_t b[2][3][7];
            #pragma unroll
            for (int ss = 0; ss < 2; ss++) {
                #pragma unroll
                for (int nt = 0; nt < 3; nt++) {
                    const uint32_t rowa = sbase + X_OFF
                        + (uint32_t)((s0 + ss) * JP + nt * 8 + nl) * ROWB;
                    asm volatile("ldmatrix.sync.aligned.m8n8.x4.shared.b16 {%0,%1,%2,%3}, [%4];"
                                 : "=r"(b[ss][nt][0]), "=r"(b[ss][nt][1]),
                                   "=r"(b[ss][nt][2]), "=r"(b[ss][nt][3])
                                 : "r"(rowa + blk * 16));
                    asm volatile("ldmatrix.sync.aligned.m8n8.x2.shared.b16 {%0,%1}, [%2];"
                                 : "=r"(b[ss][nt][4]), "=r"(b[ss][nt][5])
                                 : "r"(rowa + (4 + bl2) * 16));
                    asm volatile("ldmatrix.sync.aligned.m8n8.x1.shared.b16 {%0}, [%1];"
                                 : "=r"(b[ss][nt][6]) : "r"(rowa + 96));
                }
            }

            #pragma unroll 1
            for (int fi = 0; fi < FT_PER_W; fi++) {
                const int F = (wc * FT_PER_W + fi) * 16;
                const uint32_t abase = sbase + W1_OFF + (uint32_t)(F + rrA) * ROWB;

                uint32_t a[3][4];
                #pragma unroll
                for (int ks = 0; ks < 3; ks++) {
                    asm volatile("ldmatrix.sync.aligned.m8n8.x4.shared.b16 {%0,%1,%2,%3}, [%4];"
                                 : "=r"(a[ks][0]), "=r"(a[ks][1]),
                                   "=r"(a[ks][2]), "=r"(a[ks][3])
                                 : "r"(abase + (2 * ks + chi) * 16));
                }
                uint32_t a8[2];
                asm volatile("ldmatrix.sync.aligned.m8n8.x2.shared.b16 {%0,%1}, [%2];"
                             : "=r"(a8[0]), "=r"(a8[1]) : "r"(abase + 96));

                uint32_t ph[2][3][2];
                #pragma unroll
                for (int nt = 0; nt < 3; nt++) {
                    float c0 = 0.f, c1 = 0.f, c2 = 0.f, c3 = 0.f;
                    float d0 = 0.f, d1 = 0.f, d2 = 0.f, d3 = 0.f;
                    #pragma unroll
                    for (int ks = 0; ks < 3; ks++) {
                        asm volatile(
                            "mma.sync.aligned.m16n8k16.row.col.f32.f16.f16.f32 "
                            "{%0,%1,%2,%3}, {%4,%5,%6,%7}, {%8,%9}, {%0,%1,%2,%3};"
                            : "+f"(c0), "+f"(c1), "+f"(c2), "+f"(c3)
                            : "r"(a[ks][0]), "r"(a[ks][1]), "r"(a[ks][2]), "r"(a[ks][3]),
                              "r"(b[0][nt][2 * ks]), "r"(b[0][nt][2 * ks + 1]));
                        asm volatile(
                            "mma.sync.aligned.m16n8k16.row.col.f32.f16.f16.f32 "
                            "{%0,%1,%2,%3}, {%4,%5,%6,%7}, {%8,%9}, {%0,%1,%2,%3};"
                            : "+f"(d0), "+f"(d1), "+f"(d2), "+f"(d3)
                            : "r"(a[ks][0]), "r"(a[ks][1]), "r"(a[ks][2]), "r"(a[ks][3]),
                              "r"(b[1][nt][2 * ks]), "r"(b[1][nt][2 * ks + 1]));
                    }
                    asm volatile(
                        "mma.sync.aligned.m16n8k8.row.col.f32.f16.f16.f32 "
                        "{%0,%1,%2,%3}, {%4,%5}, {%6}, {%0,%1,%2,%3};"
                        : "+f"(c0), "+f"(c1), "+f"(c2), "+f"(c3)
                        : "r"(a8[0]), "r"(a8[1]), "r"(b[0][nt][6]));
                    asm volatile(
                        "mma.sync.aligned.m16n8k8.row.col.f32.f16.f16.f32 "
                        "{%0,%1,%2,%3}, {%4,%5}, {%6}, {%0,%1,%2,%3};"
                        : "+f"(d0), "+f"(d1), "+f"(d2), "+f"(d3)
                        : "r"(a8[0]), "r"(a8[1]), "r"(b[1][nt][6]));

                    ph[0][nt][0] = relu_pack(c0, c1);
                    ph[0][nt][1] = relu_pack(c2, c3);
                    ph[1][nt][0] = relu_pack(d0, d1);
                    ph[1][nt][1] = relu_pack(d2, d3);
                }

                // pool via MMA against all-ones B: sums the 24 rows in fp32
                float p0 = 0.f, p1 = 0.f, p2 = 0.f, p3 = 0.f;
                float q0 = 0.f, q1 = 0.f, q2 = 0.f, q3 = 0.f;
                asm volatile(
                    "mma.sync.aligned.m16n8k16.row.col.f32.f16.f16.f32 "
                    "{%0,%1,%2,%3}, {%4,%5,%6,%7}, {%8,%9}, {%0,%1,%2,%3};"
                    : "+f"(p0), "+f"(p1), "+f"(p2), "+f"(p3)
                    : "r"(ph[0][0][0]), "r"(ph[0][0][1]), "r"(ph[0][1][0]), "r"(ph[0][1][1]),
                      "r"(ONESH2), "r"(ONESH2));
                asm volatile(
                    "mma.sync.aligned.m16n8k8.row.col.f32.f16.f16.f32 "
                    "{%0,%1,%2,%3}, {%4,%5}, {%6}, {%0,%1,%2,%3};"
                    : "+f"(p0), "+f"(p1), "+f"(p2), "+f"(p3)
                    : "r"(ph[0][2][0]), "r"(ph[0][2][1]), "r"(ONESH2));
                asm volatile(
                    "mma.sync.aligned.m16n8k16.row.col.f32.f16.f16.f32 "
                    "{%0,%1,%2,%3}, {%4,%5,%6,%7}, {%8,%9}, {%0,%1,%2,%3};"
                    : "+f"(q0), "+f"(q1), "+f"(q2), "+f"(q3)
                    : "r"(ph[1][0][0]), "r"(ph[1][0][1]), "r"(ph[1][1][0]), "r"(ph[1][1][1]),
                      "r"(ONESH2), "r"(ONESH2));
                asm volatile(
                    "mma.sync.aligned.m16n8k8.row.col.f32.f16.f16.f32 "
                    "{%0,%1,%2,%3}, {%4,%5}, {%6}, {%0,%1,%2,%3};"
                    : "+f"(q0), "+f"(q1), "+f"(q2), "+f"(q3)
                    : "r"(ph[1][2][0]), "r"(ph[1][2][1]), "r"(ONESH2));
                (void)p1; (void)p3; (void)q1; (void)q3;

                if (pool_leader) {
                    char* f0 = smem + F16_OFF + s0 * F16_STRIDE + (F + prow) * 2;
                    char* f1 = smem + F16_OFF + (s0 + 1) * F16_STRIDE + (F + prow) * 2;
                    *(half*)(f0)      = __float2half(p0 * (1.0f / (float)JP));
                    *(half*)(f0 + 16) = __float2half(p2 * (1.0f / (float)JP));
                    *(half*)(f1)      = __float2half(q0 * (1.0f / (float)JP));
                    *(half*)(f1 + 16) = __float2half(q2 * (1.0f / (float)JP));
                }
            }
        }

        // ---- staging refilled; feat16 complete; X fully consumed ----
        asm volatile("cp.async.wait_group 0;" ::: "memory");
        __syncthreads();
        prev_sc = sc;
    }

    // ---- epilogue GEMM2 for the last superchunk ----
    if (wid < 2 && prev_sc >= 0) {
        float e0 = 0.f, e1 = 0.f, e2 = 0.f, e3 = 0.f;
        const uint32_t arow = sbase + F16_OFF + (uint32_t)(lane & 15) * F16_STRIDE
                            + (uint32_t)(lane >> 4) * 16;
        const uint32_t* w2f = (const uint32_t*)(smem + W2F_OFF) + (wid * KS2 * 2) * 32 + lane;
        #pragma unroll 5
        for (int ks = 0; ks < KS2; ks++) {
            uint32_t a0, a1, a2, a3;
            asm volatile("ldmatrix.sync.aligned.m8n8.x4.shared.b16 {%0,%1,%2,%3}, [%4];"
                         : "=r"(a0), "=r"(a1), "=r"(a2), "=r"(a3)
                         : "r"(arow + ks * 32));
            const uint32_t b0 = w2f[(ks * 2) * 32];
            const uint32_t b1 = w2f[(ks * 2 + 1) * 32];
            asm volatile(
                "mma.sync.aligned.m16n8k16.row.col.f32.f16.f16.f32 "
                "{%0,%1,%2,%3}, {%4,%5,%6,%7}, {%8,%9}, {%0,%1,%2,%3};"
                : "+f"(e0), "+f"(e1), "+f"(e2), "+f"(e3)
                : "r"(a0), "r"(a1), "r"(a2), "r"(a3), "r"(b0), "r"(b1));
        }
        const int n = wid * 8 + 2 * (lane & 3);
        if (n < CC) {
            const int r0 = lane >> 2;
            float2 v0 = {e0, e1}, v1 = {e2, e3};
            *(float2*)(out + (size_t)(prev_sc * SEGS + r0) * CC + n)     = v0;
            *(float2*)(out + (size_t)(prev_sc * SEGS + r0 + 8) * CC + n) = v1;
        }
    }
}

extern "C" void kernel_launch(void* const* d_in, const int* in_sizes, int n_in,
                              void* d_out, int out_size)
{
    const float* x  = (const float*)d_in[0];
    const float* W1 = (const float*)d_in[1];
    const float* W2 = (const float*)d_in[2];
    float* out = (float*)d_out;

    cudaFuncSetAttribute(classifier_mma7_kernel,
                         cudaFuncAttributeMaxDynamicSharedMemorySize, SMEM_TOTAL);
    classifier_mma7_kernel<<<GRID, NTHREADS, SMEM_TOTAL>>>(x, W1, W2, out);
}